// round 8
// baseline (speedup 1.0000x reference)
#include <cuda_runtime.h>
#include <cstdint>
#include <cstddef>

#define BB    32
#define NAA   32768
#define CC    81
#define NGG   24
#define SENT  0xFFFFFFFFu
#define NBIN  16384
#define CAP   6144
#define PPB   (NAA/2)              // pairs per batch = 16384
#define MBLK  888                  // 6 blocks/SM
#define NWRP  (MBLK*8)             // 7104 warps
#define WPBATCH (NWRP/BB)          // 222 warps per batch
#define CHUNK ((PPB + WPBATCH - 1)/WPBATCH)   // 74

// ---------------- scratch (zero-initialized at module load; every kernel that
// consumes an accumulator resets it, so each graph replay sees zeros) ----------
__device__ unsigned char      g_meta[BB*NAA];     // bit7 pos, bit6 ign, bits0-5 gi
__device__ unsigned long long g_bestkey[BB*NGG];  // reset by k_force
__device__ unsigned           g_negbits[BB*NAA];  // fully overwritten each replay
__device__ unsigned           g_hcnt[BB*NBIN];    // reset by k_select
__device__ float              g_hsum[BB*NBIN];    // reset by k_select
__device__ float              g_numpos[BB], g_posce[BB], g_regsum[BB];  // reset by k_final
__device__ float              g_topk[BB];
__device__ int                g_K[BB];

__device__ __forceinline__ unsigned redux_max(unsigned v){
    unsigned r; asm("redux.sync.max.u32 %0, %1, 0xffffffff;" : "=r"(r) : "r"(v)); return r;
}

// ---------------- K1: IoU matching (4 anchors/thread, refined-rcp iou) ---------
__global__ void __launch_bounds__(256) k_iou(const float* __restrict__ anchors,
                                             const float* __restrict__ gtb){
    __shared__ float gx0[NGG],gy0[NGG],gx1[NGG],gy1[NGG],garea[NGG];
    __shared__ unsigned long long skey[NGG];
    int b=blockIdx.y, t=threadIdx.x;
    if (t<NGG){
        float4 g=((const float4*)gtb)[b*NGG+t];
        float x0=g.x-0.5f*g.z, y0=g.y-0.5f*g.w, x1=g.x+0.5f*g.z, y1=g.y+0.5f*g.w;
        gx0[t]=x0; gy0[t]=y0; gx1[t]=x1; gy1[t]=y1; garea[t]=(x1-x0)*(y1-y0);
        skey[t]=0ull;
    }
    __syncthreads();
    int abase = blockIdx.x*1024 + t;
    float ax0[4],ay0[4],ax1[4],ay1[4],areaA[4];
    #pragma unroll
    for (int k=0;k<4;++k){
        float4 an=((const float4*)anchors)[abase+k*256];
        ax0[k]=an.x-0.5f*an.z; ay0[k]=an.y-0.5f*an.w;
        ax1[k]=an.x+0.5f*an.z; ay1[k]=an.y+0.5f*an.w;
        areaA[k]=(ax1[k]-ax0[k])*(ay1[k]-ay0[k]);
    }
    float best[4]={-1.f,-1.f,-1.f,-1.f}; int bg[4]={0,0,0,0};

    for (int g=0; g<NGG; ++g){
        float bi=-1.f; int bk=0;
        #pragma unroll
        for (int k=0;k<4;++k){
            float lx=fmaxf(ax0[k],gx0[g]), ly=fmaxf(ay0[k],gy0[g]);
            float rx=fminf(ax1[k],gx1[g]), ry=fminf(ay1[k],gy1[g]);
            float w=fmaxf(rx-lx,0.f), h=fmaxf(ry-ly,0.f);
            float inter=w*h;
            float uni=fmaxf(areaA[k]+garea[g]-inter, 1e-12f);
            float rcp; asm("rcp.approx.ftz.f32 %0, %1;" : "=f"(rcp) : "f"(uni));
            rcp = rcp * __fmaf_rn(-uni, rcp, 2.0f);     // Newton -> ~1ulp of div.rn
            float iou = inter * rcp;
            if (iou>best[k]){best[k]=iou; bg[k]=g;}
            if (iou>bi){bi=iou; bk=k;}
        }
        unsigned mb=__float_as_uint(bi);
        unsigned M=redux_max(mb);
        unsigned rk=(mb==M)? (unsigned)(((3-bk)<<5)|(31-(t&31)))+1u : 0u;
        unsigned R=redux_max(rk);
        if ((t&31)==0){
            int wl=31-(int)((R-1u)&31u), wk=3-(int)((R-1u)>>5);
            unsigned a=(unsigned)(blockIdx.x*1024 + (t&~31) + wl + wk*256);
            atomicMax(&skey[g], ((unsigned long long)M<<32) | (0xFFFFFFFFu - a));
        }
    }
    #pragma unroll
    for (int k=0;k<4;++k){
        bool pos = best[k] >= 0.5f;
        bool ign = (!pos) && (best[k] > 0.4f);
        unsigned char mB = (unsigned char)(bg[k] | (pos?0x80:(ign?0x40:0)));
        g_meta[b*NAA + abase + k*256] = mB;
    }
    __syncthreads();
    if (t<NGG) atomicMax(&g_bestkey[b*NGG+t], skey[t]);
}

// ---------------- K1b: mark forced positives + reset bestkey -------------------
__global__ void k_force(){
    int i = threadIdx.x;
    if (i < BB*NGG){
        unsigned long long k = g_bestkey[i];
        g_bestkey[i] = 0ull;                 // restore invariant for next replay
        unsigned a = 0xFFFFFFFFu - (unsigned)(k & 0xFFFFFFFFull);
        int b = i / NGG;
        size_t idx = (size_t)b*NAA + a;
        g_meta[idx] = (unsigned char)(g_meta[idx] | 0x80);  // benign dup race
    }
}

// ---------------- K2: CE + classify + reg; half-warp per row, batch-aligned ----
__global__ void __launch_bounds__(256,6) k_main(const float* __restrict__ cls,
                                                const float* __restrict__ box,
                                                const float* __restrict__ anchors,
                                                const float* __restrict__ gtb,
                                                const int*   __restrict__ gtl){
    const int lane = threadIdx.x & 31;
    const int l16  = lane & 15;
    const int h    = lane >> 4;
    const unsigned leader = (unsigned)(h << 4);
    const int W = blockIdx.x*8 + (threadIdx.x>>5);
    const int b      = W / WPBATCH;
    const int within = W - b*WPBATCH;
    int lbeg = within*CHUNK;
    int lend = min(lbeg + CHUNK, PPB);
    if (lbeg >= lend) return;

    float l_np=0.f, l_ce=0.f, l_rg=0.f;
    const int pbeg = b*PPB + lbeg;
    const int pend = b*PPB + lend;
    const float* rp = cls + (size_t)pbeg*162 + h*81 + l16;

    for (int p = pbeg; p < pend; ++p, rp += 162){
        unsigned mm = reinterpret_cast<const unsigned short*>(g_meta)[p];
        float v0 = rp[0],  v1 = rp[16], v2 = rp[32], v3 = rp[48], v4 = rp[64];
        float v5 = (l16==0) ? rp[80] : 0.f;

        float s = __expf(v0) + __expf(v1) + __expf(v2) + __expf(v3) + __expf(v4);
        if (l16==0) s += __expf(v5);
        s += __shfl_xor_sync(0xFFFFFFFFu, s, 1);
        s += __shfl_xor_sync(0xFFFFFFFFu, s, 2);
        s += __shfl_xor_sync(0xFFFFFFFFu, s, 4);
        s += __shfl_xor_sync(0xFFFFFFFFu, s, 8);
        float lse = __logf(s);

        unsigned mb = (mm >> (h*8)) & 0xFFu;
        bool pos = (mb & 0x80u) != 0;
        bool ign = (mb & 0x40u) != 0;

        if (l16==0){
            int rowh = 2*p + h;
            if (pos | ign) g_negbits[rowh] = SENT;
            else {
                float ce = fmaxf(lse - v0, 0.f);        // v0 = row[0] on leader
                unsigned bits = __float_as_uint(ce);
                g_negbits[rowh] = bits;
                atomicAdd(&g_hcnt[b*NBIN + (bits>>18)], 1u);
                atomicAdd(&g_hsum[b*NBIN + (bits>>18)], ce);
            }
        }
        if (__any_sync(0xFFFFFFFFu, pos)){               // rare, warp-uniform branch
            int gi = (int)(mb & 0x3Fu);
            int tl = 0;
            if (l16==0 && pos) tl = gtl[b*NGG + gi];
            int tgt = __shfl_sync(0xFFFFFFFFu, tl, leader);
            int slot = tgt >> 4;
            float val = (slot==0)?v0:(slot==1)?v1:(slot==2)?v2:(slot==3)?v3:(slot==4)?v4:v5;
            float vt = __shfl_sync(0xFFFFFFFFu, val, (unsigned)((tgt&15))|leader);
            if (l16==0 && pos){
                int a = (2*p + h) & (NAA-1);
                l_np += 1.f;
                l_ce += fmaxf(lse - vt, 0.f);
                float4 an = ((const float4*)anchors)[a];
                float4 g  = ((const float4*)gtb)[b*NGG + gi];
                float tx = (g.x - an.x) / an.z / 0.1f;
                float ty = (g.y - an.y) / an.w / 0.1f;
                float tw = __logf(g.z / an.z) / 0.2f;
                float th = __logf(g.w / an.w) / 0.2f;
                float4 bp = ((const float4*)box)[(size_t)b*NAA + a];
                float d0=bp.x-tx, d1=bp.y-ty, d2=bp.z-tw, d3=bp.w-th;
                float e0=fabsf(d0), e1=fabsf(d1), e2=fabsf(d2), e3=fabsf(d3);
                l_rg += ((e0<1.f)?0.5f*d0*d0:e0-0.5f) + ((e1<1.f)?0.5f*d1*d1:e1-0.5f)
                      + ((e2<1.f)?0.5f*d2*d2:e2-0.5f) + ((e3<1.f)?0.5f*d3*d3:e3-0.5f);
            }
        }
    }
    if (__any_sync(0xFFFFFFFFu, l_np != 0.f)){
        float a0=l_np, c0=l_ce, r0=l_rg;
        a0 += __shfl_down_sync(0xFFFFFFFFu, a0, 16);
        c0 += __shfl_down_sync(0xFFFFFFFFu, c0, 16);
        r0 += __shfl_down_sync(0xFFFFFFFFu, r0, 16);
        if (lane==0){
            atomicAdd(&g_numpos[b], a0);
            atomicAdd(&g_posce[b],  c0);
            atomicAdd(&g_regsum[b], r0);
        }
    }
}

// ---------------- warp-scale select over 512 smem bins -------------------------
__device__ void warp_select(const unsigned* cnt, const float* fs, int K,
                            int* o_bin, int* o_k, float* o_S){
    int l = threadIdx.x;
    int base = l*16;
    unsigned c=0; float f=0.f;
    #pragma unroll
    for (int j=0;j<16;++j){ c+=cnt[base+j]; f+=fs[base+j]; }
    unsigned ci=c; float fi=f;
    #pragma unroll
    for (int off=1;off<32;off<<=1){
        unsigned uc=__shfl_up_sync(0xFFFFFFFFu,ci,off);
        float    uf=__shfl_up_sync(0xFFFFFFFFu,fi,off);
        if (l>=off){ ci+=uc; fi+=uf; }
    }
    unsigned total=__shfl_sync(0xFFFFFFFFu,ci,31);
    float    ftot =__shfl_sync(0xFFFFFFFFu,fi,31);
    unsigned SA=total-ci; float FA=ftot-fi;
    if (SA < (unsigned)K && (unsigned)K <= SA + c){
        unsigned run=SA; float fab=FA;
        for (int j=15;j>=0;--j){
            unsigned cb=cnt[base+j];
            if (run + cb >= (unsigned)K){ *o_bin=base+j; *o_k=(int)((unsigned)K-run); *o_S=fab; break; }
            run += cb; fab += fs[base+j];
        }
    }
}

// ---------------- K3: exact top-K (K = min(3*num_pos, neg); num_pos >= 1) ------
__global__ void __launch_bounds__(1024) k_select(){
    int b=blockIdx.x, t=threadIdx.x;
    int lane=t&31, warp=t>>5;
    unsigned* cnt = g_hcnt + b*NBIN;
    float*    fsm = g_hsum + b*NBIN;
    __shared__ unsigned swc[32]; __shared__ float swf[32];
    __shared__ int s_t1, s_k1;  __shared__ float s_S1;
    __shared__ int s_bin, s_k;  __shared__ float s_S;
    __shared__ int s_n;
    __shared__ unsigned cnt2[512]; __shared__ float fs2[512];
    __shared__ unsigned slist[CAP];

    int base=t*16;
    unsigned c=0; float f=0.f;
    #pragma unroll
    for (int j=0;j<16;++j){ c+=cnt[base+j]; f+=fsm[base+j]; }
    unsigned ci=c; float fi=f;
    #pragma unroll
    for (int off=1;off<32;off<<=1){
        unsigned uc=__shfl_up_sync(0xFFFFFFFFu,ci,off);
        float    uf=__shfl_up_sync(0xFFFFFFFFu,fi,off);
        if (lane>=off){ ci+=uc; fi+=uf; }
    }
    if (lane==31){ swc[warp]=ci; swf[warp]=fi; }
    __syncthreads();
    if (t<32){
        unsigned u=swc[t]; float g=swf[t];
        #pragma unroll
        for (int off=1;off<32;off<<=1){
            unsigned uu=__shfl_up_sync(0xFFFFFFFFu,u,off);
            float    gg=__shfl_up_sync(0xFFFFFFFFu,g,off);
            if (t>=off){ u+=uu; g+=gg; }
        }
        swc[t]=u; swf[t]=g;
    }
    __syncthreads();
    unsigned P = ci + (warp ? swc[warp-1] : 0u);
    float    FP= fi + (warp ? swf[warp-1] : 0.f);
    unsigned total=swc[31]; float ftot=swf[31];

    float np = g_numpos[b];
    int negcnt = (int)total;
    int K = min(3*(int)np, negcnt);
    if (t==0) g_K[b] = K;
    if (K<=0){
        if (t==0) g_topk[b]=0.f;
        // reset hist for next replay, then exit
        #pragma unroll
        for (int j=0;j<16;++j){ cnt[base+j]=0u; fsm[base+j]=0.f; }
        return;
    }

    unsigned SA = total - P; float FA = ftot - FP;
    if (SA < (unsigned)K && (unsigned)K <= SA + c){
        unsigned run=SA; float fab=FA;
        for (int j=15;j>=0;--j){
            unsigned cb=cnt[base+j];
            if (run + cb >= (unsigned)K){ s_t1=base+j; s_k1=(int)((unsigned)K-run); s_S1=fab; break; }
            run += cb; fab += fsm[base+j];
        }
    }
    if (t==0) s_n=0;
    for (int i=t;i<512;i+=1024){ cnt2[i]=0u; fs2[i]=0.f; }
    __syncthreads();
    int t1=s_t1, k1=s_k1; float S1=s_S1;
    unsigned cT1 = cnt[t1];
    const unsigned* vals = g_negbits + b*NAA;
    bool collect = (cT1 <= CAP);
    if (collect){
        for (int i=t;i<NAA;i+=1024){
            unsigned v=vals[i];
            if ((v>>18)==(unsigned)t1){ int p=atomicAdd(&s_n,1); slist[p]=v; }
        }
    }
    __syncthreads();
    int n=s_n;
    if (collect){
        for (int i=t;i<n;i+=1024){
            unsigned v=slist[i];
            atomicAdd(&cnt2[(v>>9)&511u],1u); atomicAdd(&fs2[(v>>9)&511u],__uint_as_float(v));
        }
    } else {
        for (int i=t;i<NAA;i+=1024){
            unsigned v=vals[i];
            if ((v>>18)==(unsigned)t1){ atomicAdd(&cnt2[(v>>9)&511u],1u); atomicAdd(&fs2[(v>>9)&511u],__uint_as_float(v)); }
        }
    }
    __syncthreads();
    if (t<32) warp_select(cnt2, fs2, k1, &s_bin, &s_k, &s_S);
    __syncthreads();
    int t2=s_bin, k2=s_k; float S2=s_S;
    for (int i=t;i<512;i+=1024){ cnt2[i]=0u; fs2[i]=0.f; }
    __syncthreads();
    unsigned pfx = ((unsigned)t1<<9) | (unsigned)t2;
    if (collect){
        for (int i=t;i<n;i+=1024){
            unsigned v=slist[i];
            if ((v>>9)==pfx){ atomicAdd(&cnt2[v&511u],1u); atomicAdd(&fs2[v&511u],__uint_as_float(v)); }
        }
    } else {
        for (int i=t;i<NAA;i+=1024){
            unsigned v=vals[i];
            if ((v>>9)==pfx){ atomicAdd(&cnt2[v&511u],1u); atomicAdd(&fs2[v&511u],__uint_as_float(v)); }
        }
    }
    __syncthreads();
    if (t<32) warp_select(cnt2, fs2, k2, &s_bin, &s_k, &s_S);
    __syncthreads();
    if (t==0){
        unsigned tv = (pfx<<9) | (unsigned)s_bin;
        g_topk[b] = S1 + S2 + s_S + (float)s_k * __uint_as_float(tv);
    }
    __syncthreads();                       // all reads of cnt/fsm complete
    #pragma unroll
    for (int j=0;j<16;++j){ cnt[base+j]=0u; fsm[base+j]=0.f; }   // reset for next replay
}

// ---------------- K4: warp-parallel final reduce (+ accumulator reset) ---------
__global__ void k_final(float* __restrict__ out){
    int b = threadIdx.x;                   // 32 threads
    float np = g_numpos[b];
    float pc = g_posce[b];
    float rg = g_regsum[b];
    g_numpos[b]=0.f; g_posce[b]=0.f; g_regsum[b]=0.f;   // reset for next replay
    int K = g_K[b];
    float cls = (K>0) ? (pc + g_topk[b]) / fmaxf(np + (float)K, 1.f)
                      : pc / fmaxf(np, 1.f);
    float reg = rg / fmaxf(np*4.f, 1.f);   // num_pos >= 1 always
    #pragma unroll
    for (int off=16; off; off>>=1){
        cls += __shfl_xor_sync(0xFFFFFFFFu, cls, off);
        reg += __shfl_xor_sync(0xFFFFFFFFu, reg, off);
        np  += __shfl_xor_sync(0xFFFFFFFFu, np,  off);
    }
    if (b==0){
        out[0]=cls/(float)BB; out[1]=reg/(float)BB; out[2]=np/(float)BB;
    }
}

// ---------------- launch -------------------------------------------------------
extern "C" void kernel_launch(void* const* d_in, const int* in_sizes, int n_in,
                              void* d_out, int out_size) {
    const float* cls=nullptr; const float* box=nullptr; const float* anc=nullptr;
    const float* gtb=nullptr; const int* gtl=nullptr;
    for (int i=0;i<n_in;++i){
        long sz=in_sizes[i];
        if      (sz==(long)BB*NAA*CC) cls=(const float*)d_in[i];
        else if (sz==(long)BB*NAA*4)  box=(const float*)d_in[i];
        else if (sz==(long)NAA*4)     anc=(const float*)d_in[i];
        else if (sz==(long)BB*NGG*4)  gtb=(const float*)d_in[i];
        else if (sz==(long)BB*NGG)    gtl=(const int*)d_in[i];
    }
    k_iou<<<dim3(NAA/1024, BB), 256>>>(anc, gtb);
    k_force<<<1, BB*NGG>>>();
    k_main<<<MBLK, 256>>>(cls, box, anc, gtb, gtl);
    k_select<<<BB, 1024>>>();
    k_final<<<1, 32>>>((float*)d_out);
}

// round 9
// speedup vs baseline: 1.0904x; 1.0904x over previous
#include <cuda_runtime.h>
#include <cstdint>
#include <cstddef>

#define BB    32
#define NAA   32768
#define CC    81
#define NGG   24
#define SENT  0xFFFFFFFFu
#define NBIN  16384
#define CAP   6144
#define PPB   (NAA/2)              // pairs per batch = 16384
#define MBLK  888                  // 6 blocks/SM
#define NWRP  (MBLK*8)             // 7104 warps
#define WPBATCH (NWRP/BB)          // 222 warps per batch
#define CHUNK ((PPB + WPBATCH - 1)/WPBATCH)   // 74

// ---------------- scratch (zero-initialized at module load; every kernel that
// consumes an accumulator resets it, so each graph replay sees zeros) ----------
__device__ unsigned char      g_meta[BB*NAA];     // bit7 pos, bit6 ign, bits0-5 gi
__device__ unsigned long long g_bestkey[BB*NGG];  // reset by k_force
__device__ __align__(16) unsigned g_negbits[BB*NAA];  // fully overwritten each replay
__device__ __align__(16) unsigned g_hcnt[BB*NBIN];    // reset by k_select
__device__ __align__(16) float    g_hsum[BB*NBIN];    // reset by k_select
__device__ float              g_numpos[BB], g_posce[BB], g_regsum[BB];  // reset by k_final
__device__ float              g_topk[BB];
__device__ int                g_K[BB];

__device__ __forceinline__ unsigned redux_max(unsigned v){
    unsigned r; asm("redux.sync.max.u32 %0, %1, 0xffffffff;" : "=r"(r) : "r"(v)); return r;
}

// ---------------- K1: IoU matching (4 anchors/thread, refined-rcp iou) ---------
__global__ void __launch_bounds__(256) k_iou(const float* __restrict__ anchors,
                                             const float* __restrict__ gtb){
    __shared__ float gx0[NGG],gy0[NGG],gx1[NGG],gy1[NGG],garea[NGG];
    __shared__ unsigned long long skey[NGG];
    int b=blockIdx.y, t=threadIdx.x;
    if (t<NGG){
        float4 g=((const float4*)gtb)[b*NGG+t];
        float x0=g.x-0.5f*g.z, y0=g.y-0.5f*g.w, x1=g.x+0.5f*g.z, y1=g.y+0.5f*g.w;
        gx0[t]=x0; gy0[t]=y0; gx1[t]=x1; gy1[t]=y1; garea[t]=(x1-x0)*(y1-y0);
        skey[t]=0ull;
    }
    __syncthreads();
    int abase = blockIdx.x*1024 + t;
    float ax0[4],ay0[4],ax1[4],ay1[4],areaA[4];
    #pragma unroll
    for (int k=0;k<4;++k){
        float4 an=((const float4*)anchors)[abase+k*256];
        ax0[k]=an.x-0.5f*an.z; ay0[k]=an.y-0.5f*an.w;
        ax1[k]=an.x+0.5f*an.z; ay1[k]=an.y+0.5f*an.w;
        areaA[k]=(ax1[k]-ax0[k])*(ay1[k]-ay0[k]);
    }
    float best[4]={-1.f,-1.f,-1.f,-1.f}; int bg[4]={0,0,0,0};

    for (int g=0; g<NGG; ++g){
        float bi=-1.f; int bk=0;
        #pragma unroll
        for (int k=0;k<4;++k){
            float lx=fmaxf(ax0[k],gx0[g]), ly=fmaxf(ay0[k],gy0[g]);
            float rx=fminf(ax1[k],gx1[g]), ry=fminf(ay1[k],gy1[g]);
            float w=fmaxf(rx-lx,0.f), h=fmaxf(ry-ly,0.f);
            float inter=w*h;
            float uni=fmaxf(areaA[k]+garea[g]-inter, 1e-12f);
            float rcp; asm("rcp.approx.ftz.f32 %0, %1;" : "=f"(rcp) : "f"(uni));
            rcp = rcp * __fmaf_rn(-uni, rcp, 2.0f);     // Newton -> ~1ulp of div.rn
            float iou = inter * rcp;
            if (iou>best[k]){best[k]=iou; bg[k]=g;}
            if (iou>bi){bi=iou; bk=k;}
        }
        unsigned mb=__float_as_uint(bi);
        unsigned M=redux_max(mb);
        unsigned rk=(mb==M)? (unsigned)(((3-bk)<<5)|(31-(t&31)))+1u : 0u;
        unsigned R=redux_max(rk);
        if ((t&31)==0){
            int wl=31-(int)((R-1u)&31u), wk=3-(int)((R-1u)>>5);
            unsigned a=(unsigned)(blockIdx.x*1024 + (t&~31) + wl + wk*256);
            atomicMax(&skey[g], ((unsigned long long)M<<32) | (0xFFFFFFFFu - a));
        }
    }
    #pragma unroll
    for (int k=0;k<4;++k){
        bool pos = best[k] >= 0.5f;
        bool ign = (!pos) && (best[k] > 0.4f);
        unsigned char mB = (unsigned char)(bg[k] | (pos?0x80:(ign?0x40:0)));
        g_meta[b*NAA + abase + k*256] = mB;
    }
    __syncthreads();
    if (t<NGG) atomicMax(&g_bestkey[b*NGG+t], skey[t]);
}

// ---------------- K1b: mark forced positives + reset bestkey -------------------
__global__ void k_force(){
    int i = threadIdx.x;
    if (i < BB*NGG){
        unsigned long long k = g_bestkey[i];
        g_bestkey[i] = 0ull;                 // restore invariant for next replay
        unsigned a = 0xFFFFFFFFu - (unsigned)(k & 0xFFFFFFFFull);
        int b = i / NGG;
        size_t idx = (size_t)b*NAA + a;
        g_meta[idx] = (unsigned char)(g_meta[idx] | 0x80);  // benign dup race
    }
}

// ---------------- K2: CE + classify + reg; half-warp per row, batch-aligned ----
__global__ void __launch_bounds__(256,6) k_main(const float* __restrict__ cls,
                                                const float* __restrict__ box,
                                                const float* __restrict__ anchors,
                                                const float* __restrict__ gtb,
                                                const int*   __restrict__ gtl){
    const int lane = threadIdx.x & 31;
    const int l16  = lane & 15;
    const int h    = lane >> 4;
    const unsigned leader = (unsigned)(h << 4);
    const int W = blockIdx.x*8 + (threadIdx.x>>5);
    const int b      = W / WPBATCH;
    const int within = W - b*WPBATCH;
    int lbeg = within*CHUNK;
    int lend = min(lbeg + CHUNK, PPB);
    if (lbeg >= lend) return;

    float l_np=0.f, l_ce=0.f, l_rg=0.f;
    const int pbeg = b*PPB + lbeg;
    const int pend = b*PPB + lend;
    const float* rp = cls + (size_t)pbeg*162 + h*81 + l16;

    for (int p = pbeg; p < pend; ++p, rp += 162){
        unsigned mm = reinterpret_cast<const unsigned short*>(g_meta)[p];
        float v0 = rp[0],  v1 = rp[16], v2 = rp[32], v3 = rp[48], v4 = rp[64];
        float v5 = (l16==0) ? rp[80] : 0.f;

        float s = __expf(v0) + __expf(v1) + __expf(v2) + __expf(v3) + __expf(v4);
        if (l16==0) s += __expf(v5);
        s += __shfl_xor_sync(0xFFFFFFFFu, s, 1);
        s += __shfl_xor_sync(0xFFFFFFFFu, s, 2);
        s += __shfl_xor_sync(0xFFFFFFFFu, s, 4);
        s += __shfl_xor_sync(0xFFFFFFFFu, s, 8);
        float lse = __logf(s);

        unsigned mb = (mm >> (h*8)) & 0xFFu;
        bool pos = (mb & 0x80u) != 0;
        bool ign = (mb & 0x40u) != 0;

        if (l16==0){
            int rowh = 2*p + h;
            if (pos | ign) g_negbits[rowh] = SENT;
            else {
                float ce = fmaxf(lse - v0, 0.f);        // v0 = row[0] on leader
                unsigned bits = __float_as_uint(ce);
                g_negbits[rowh] = bits;
                atomicAdd(&g_hcnt[b*NBIN + (bits>>18)], 1u);
                atomicAdd(&g_hsum[b*NBIN + (bits>>18)], ce);
            }
        }
        if (__any_sync(0xFFFFFFFFu, pos)){               // rare, warp-uniform branch
            int gi = (int)(mb & 0x3Fu);
            int tl = 0;
            if (l16==0 && pos) tl = gtl[b*NGG + gi];
            int tgt = __shfl_sync(0xFFFFFFFFu, tl, leader);
            int slot = tgt >> 4;
            float val = (slot==0)?v0:(slot==1)?v1:(slot==2)?v2:(slot==3)?v3:(slot==4)?v4:v5;
            float vt = __shfl_sync(0xFFFFFFFFu, val, (unsigned)((tgt&15))|leader);
            if (l16==0 && pos){
                int a = (2*p + h) & (NAA-1);
                l_np += 1.f;
                l_ce += fmaxf(lse - vt, 0.f);
                float4 an = ((const float4*)anchors)[a];
                float4 g  = ((const float4*)gtb)[b*NGG + gi];
                float tx = (g.x - an.x) / an.z / 0.1f;
                float ty = (g.y - an.y) / an.w / 0.1f;
                float tw = __logf(g.z / an.z) / 0.2f;
                float th = __logf(g.w / an.w) / 0.2f;
                float4 bp = ((const float4*)box)[(size_t)b*NAA + a];
                float d0=bp.x-tx, d1=bp.y-ty, d2=bp.z-tw, d3=bp.w-th;
                float e0=fabsf(d0), e1=fabsf(d1), e2=fabsf(d2), e3=fabsf(d3);
                l_rg += ((e0<1.f)?0.5f*d0*d0:e0-0.5f) + ((e1<1.f)?0.5f*d1*d1:e1-0.5f)
                      + ((e2<1.f)?0.5f*d2*d2:e2-0.5f) + ((e3<1.f)?0.5f*d3*d3:e3-0.5f);
            }
        }
    }
    if (__any_sync(0xFFFFFFFFu, l_np != 0.f)){
        float a0=l_np, c0=l_ce, r0=l_rg;
        a0 += __shfl_down_sync(0xFFFFFFFFu, a0, 16);
        c0 += __shfl_down_sync(0xFFFFFFFFu, c0, 16);
        r0 += __shfl_down_sync(0xFFFFFFFFu, r0, 16);
        if (lane==0){
            atomicAdd(&g_numpos[b], a0);
            atomicAdd(&g_posce[b],  c0);
            atomicAdd(&g_regsum[b], r0);
        }
    }
}

// ---------------- warp-scale select over 512 smem bins -------------------------
__device__ void warp_select(const unsigned* cnt, const float* fs, int K,
                            int* o_bin, int* o_k, float* o_S){
    int l = threadIdx.x;
    int base = l*16;
    unsigned c=0; float f=0.f;
    #pragma unroll
    for (int j=0;j<16;++j){ c+=cnt[base+j]; f+=fs[base+j]; }
    unsigned ci=c; float fi=f;
    #pragma unroll
    for (int off=1;off<32;off<<=1){
        unsigned uc=__shfl_up_sync(0xFFFFFFFFu,ci,off);
        float    uf=__shfl_up_sync(0xFFFFFFFFu,fi,off);
        if (l>=off){ ci+=uc; fi+=uf; }
    }
    unsigned total=__shfl_sync(0xFFFFFFFFu,ci,31);
    float    ftot =__shfl_sync(0xFFFFFFFFu,fi,31);
    unsigned SA=total-ci; float FA=ftot-fi;
    if (SA < (unsigned)K && (unsigned)K <= SA + c){
        unsigned run=SA; float fab=FA;
        for (int j=15;j>=0;--j){
            unsigned cb=cnt[base+j];
            if (run + cb >= (unsigned)K){ *o_bin=base+j; *o_k=(int)((unsigned)K-run); *o_S=fab; break; }
            run += cb; fab += fs[base+j];
        }
    }
}

// ---------------- K3: exact top-K; all global traffic 128-bit ------------------
__global__ void __launch_bounds__(1024) k_select(){
    int b=blockIdx.x, t=threadIdx.x;
    int lane=t&31, warp=t>>5;
    unsigned* cnt = g_hcnt + b*NBIN;
    float*    fsm = g_hsum + b*NBIN;
    __shared__ unsigned swc[32]; __shared__ float swf[32];
    __shared__ int s_t1, s_k1;  __shared__ float s_S1;
    __shared__ int s_bin, s_k;  __shared__ float s_S;
    __shared__ int s_n;
    __shared__ unsigned cnt2[512]; __shared__ float fs2[512];
    __shared__ unsigned slist[CAP];

    // ---- level-1: load this thread's 16 bins into registers (128-bit loads) ----
    int base = t*16;
    unsigned cb[16]; float fb[16];
    {
        const uint4*  c4 = (const uint4*) (cnt + base);
        const float4* f4 = (const float4*)(fsm + base);
        #pragma unroll
        for (int q=0;q<4;++q){
            uint4  u = c4[q];
            float4 g = f4[q];
            cb[q*4+0]=u.x; cb[q*4+1]=u.y; cb[q*4+2]=u.z; cb[q*4+3]=u.w;
            fb[q*4+0]=g.x; fb[q*4+1]=g.y; fb[q*4+2]=g.z; fb[q*4+3]=g.w;
        }
    }
    unsigned c=0; float f=0.f;
    #pragma unroll
    for (int j=0;j<16;++j){ c+=cb[j]; f+=fb[j]; }
    unsigned ci=c; float fi=f;
    #pragma unroll
    for (int off=1;off<32;off<<=1){
        unsigned uc=__shfl_up_sync(0xFFFFFFFFu,ci,off);
        float    uf=__shfl_up_sync(0xFFFFFFFFu,fi,off);
        if (lane>=off){ ci+=uc; fi+=uf; }
    }
    if (lane==31){ swc[warp]=ci; swf[warp]=fi; }
    __syncthreads();
    if (t<32){
        unsigned u=swc[t]; float g=swf[t];
        #pragma unroll
        for (int off=1;off<32;off<<=1){
            unsigned uu=__shfl_up_sync(0xFFFFFFFFu,u,off);
            float    gg=__shfl_up_sync(0xFFFFFFFFu,g,off);
            if (t>=off){ u+=uu; g+=gg; }
        }
        swc[t]=u; swf[t]=g;
    }
    __syncthreads();
    unsigned P = ci + (warp ? swc[warp-1] : 0u);
    float    FP= fi + (warp ? swf[warp-1] : 0.f);
    unsigned total=swc[31]; float ftot=swf[31];

    float np = g_numpos[b];
    int negcnt = (int)total;
    int K = min(3*(int)np, negcnt);
    if (t==0) g_K[b] = K;

    if (K > 0){                              // block-uniform branch
        unsigned SA = total - P; float FA = ftot - FP;
        if (SA < (unsigned)K && (unsigned)K <= SA + c){
            unsigned run=SA; float fab=FA;
            #pragma unroll
            for (int j=15;j>=0;--j){
                unsigned cbj=cb[j];
                if (run + cbj >= (unsigned)K){ s_t1=base+j; s_k1=(int)((unsigned)K-run); s_S1=fab; break; }
                run += cbj; fab += fb[j];
            }
        }
        if (t==0) s_n=0;
        for (int i=t;i<512;i+=1024){ cnt2[i]=0u; fs2[i]=0.f; }
        __syncthreads();
        int t1=s_t1, k1=s_k1; float S1=s_S1;
        unsigned cT1 = cnt[t1];
        const unsigned* vals = g_negbits + b*NAA;
        bool collect = (cT1 <= CAP);
        if (collect){
            const uint4* v4 = (const uint4*)vals;
            for (int i=t;i<NAA/4;i+=1024){
                uint4 v = v4[i];
                if ((v.x>>18)==(unsigned)t1){ int p=atomicAdd(&s_n,1); slist[p]=v.x; }
                if ((v.y>>18)==(unsigned)t1){ int p=atomicAdd(&s_n,1); slist[p]=v.y; }
                if ((v.z>>18)==(unsigned)t1){ int p=atomicAdd(&s_n,1); slist[p]=v.z; }
                if ((v.w>>18)==(unsigned)t1){ int p=atomicAdd(&s_n,1); slist[p]=v.w; }
            }
        }
        __syncthreads();
        int n=s_n;
        if (collect){
            for (int i=t;i<n;i+=1024){
                unsigned v=slist[i];
                atomicAdd(&cnt2[(v>>9)&511u],1u); atomicAdd(&fs2[(v>>9)&511u],__uint_as_float(v));
            }
        } else {
            for (int i=t;i<NAA;i+=1024){
                unsigned v=vals[i];
                if ((v>>18)==(unsigned)t1){ atomicAdd(&cnt2[(v>>9)&511u],1u); atomicAdd(&fs2[(v>>9)&511u],__uint_as_float(v)); }
            }
        }
        __syncthreads();
        if (t<32) warp_select(cnt2, fs2, k1, &s_bin, &s_k, &s_S);
        __syncthreads();
        int t2=s_bin, k2=s_k; float S2=s_S;
        for (int i=t;i<512;i+=1024){ cnt2[i]=0u; fs2[i]=0.f; }
        __syncthreads();
        unsigned pfx = ((unsigned)t1<<9) | (unsigned)t2;
        if (collect){
            for (int i=t;i<n;i+=1024){
                unsigned v=slist[i];
                if ((v>>9)==pfx){ atomicAdd(&cnt2[v&511u],1u); atomicAdd(&fs2[v&511u],__uint_as_float(v)); }
            }
        } else {
            for (int i=t;i<NAA;i+=1024){
                unsigned v=vals[i];
                if ((v>>9)==pfx){ atomicAdd(&cnt2[v&511u],1u); atomicAdd(&fs2[v&511u],__uint_as_float(v)); }
            }
        }
        __syncthreads();
        if (t<32) warp_select(cnt2, fs2, k2, &s_bin, &s_k, &s_S);
        __syncthreads();
        if (t==0){
            unsigned tv = (pfx<<9) | (unsigned)s_bin;
            g_topk[b] = S1 + S2 + s_S + (float)s_k * __uint_as_float(tv);
        }
    } else {
        if (t==0) g_topk[b]=0.f;
    }

    // ---- reset this batch's hist for the next replay (128-bit stores) ----------
    {
        uint4*  c4 = (uint4*) (cnt + base);
        float4* f4 = (float4*)(fsm + base);
        uint4  uz = make_uint4(0u,0u,0u,0u);
        float4 fz = make_float4(0.f,0.f,0.f,0.f);
        #pragma unroll
        for (int q=0;q<4;++q){ c4[q]=uz; f4[q]=fz; }
    }
}

// ---------------- K4: warp-parallel final reduce (+ accumulator reset) ---------
__global__ void k_final(float* __restrict__ out){
    int b = threadIdx.x;                   // 32 threads
    float np = g_numpos[b];
    float pc = g_posce[b];
    float rg = g_regsum[b];
    g_numpos[b]=0.f; g_posce[b]=0.f; g_regsum[b]=0.f;   // reset for next replay
    int K = g_K[b];
    float cls = (K>0) ? (pc + g_topk[b]) / fmaxf(np + (float)K, 1.f)
                      : pc / fmaxf(np, 1.f);
    float reg = rg / fmaxf(np*4.f, 1.f);   // num_pos >= 1 always
    #pragma unroll
    for (int off=16; off; off>>=1){
        cls += __shfl_xor_sync(0xFFFFFFFFu, cls, off);
        reg += __shfl_xor_sync(0xFFFFFFFFu, reg, off);
        np  += __shfl_xor_sync(0xFFFFFFFFu, np,  off);
    }
    if (b==0){
        out[0]=cls/(float)BB; out[1]=reg/(float)BB; out[2]=np/(float)BB;
    }
}

// ---------------- launch -------------------------------------------------------
extern "C" void kernel_launch(void* const* d_in, const int* in_sizes, int n_in,
                              void* d_out, int out_size) {
    const float* cls=nullptr; const float* box=nullptr; const float* anc=nullptr;
    const float* gtb=nullptr; const int* gtl=nullptr;
    for (int i=0;i<n_in;++i){
        long sz=in_sizes[i];
        if      (sz==(long)BB*NAA*CC) cls=(const float*)d_in[i];
        else if (sz==(long)BB*NAA*4)  box=(const float*)d_in[i];
        else if (sz==(long)NAA*4)     anc=(const float*)d_in[i];
        else if (sz==(long)BB*NGG*4)  gtb=(const float*)d_in[i];
        else if (sz==(long)BB*NGG)    gtl=(const int*)d_in[i];
    }
    k_iou<<<dim3(NAA/1024, BB), 256>>>(anc, gtb);
    k_force<<<1, BB*NGG>>>();
    k_main<<<MBLK, 256>>>(cls, box, anc, gtb, gtl);
    k_select<<<BB, 1024>>>();
    k_final<<<1, 32>>>((float*)d_out);
}

// round 10
// speedup vs baseline: 1.4779x; 1.3554x over previous
#include <cuda_runtime.h>
#include <cstdint>
#include <cstddef>

#define BB    32
#define NAA   32768
#define CC    81
#define NGG   24
#define SENT  0xFFFFFFFFu
#define NBIN  16384
#define CAP   6144
#define PPB   (NAA/2)              // pairs per batch = 16384
#define MBLK  740                  // 5 blocks/SM
#define NWRP  (MBLK*8)             // 5920 warps
#define WPBATCH (NWRP/BB)          // 185 warps per batch
#define CHUNK 90                   // even; 182 warps cover 16384 pairs

// ---------------- scratch (zero-init at load; consumers reset for replay) ------
__device__ unsigned char      g_meta[BB*NAA];     // bit7 pos, bit6 ign, bits0-5 gi
__device__ unsigned long long g_bestkey[BB*NGG];  // reset by k_iou last block
__device__ __align__(16) unsigned g_negbits[BB*NAA];
__device__ __align__(16) unsigned g_hcnt[BB*NBIN];    // reset by k_select
__device__ __align__(16) float    g_hsum[BB*NBIN];    // reset by k_select
__device__ float              g_numpos[BB], g_posce[BB], g_regsum[BB];  // reset by k_select last block
__device__ float              g_topk[BB];
__device__ int                g_K[BB];
__device__ int                g_ctr1, g_ctr2;     // self-resetting done-counters

__device__ __forceinline__ unsigned redux_max(unsigned v){
    unsigned r; asm("redux.sync.max.u32 %0, %1, 0xffffffff;" : "=r"(r) : "r"(v)); return r;
}

// ---------------- K1: IoU matching + (last block) forced positives -------------
__global__ void __launch_bounds__(256) k_iou(const float* __restrict__ anchors,
                                             const float* __restrict__ gtb){
    __shared__ float gx0[NGG],gy0[NGG],gx1[NGG],gy1[NGG],garea[NGG];
    __shared__ unsigned long long skey[NGG];
    __shared__ int s_last;
    int b=blockIdx.y, t=threadIdx.x;
    if (t<NGG){
        float4 g=((const float4*)gtb)[b*NGG+t];
        float x0=g.x-0.5f*g.z, y0=g.y-0.5f*g.w, x1=g.x+0.5f*g.z, y1=g.y+0.5f*g.w;
        gx0[t]=x0; gy0[t]=y0; gx1[t]=x1; gy1[t]=y1; garea[t]=(x1-x0)*(y1-y0);
        skey[t]=0ull;
    }
    __syncthreads();
    int abase = blockIdx.x*1024 + t;
    float ax0[4],ay0[4],ax1[4],ay1[4],areaA[4];
    #pragma unroll
    for (int k=0;k<4;++k){
        float4 an=((const float4*)anchors)[abase+k*256];
        ax0[k]=an.x-0.5f*an.z; ay0[k]=an.y-0.5f*an.w;
        ax1[k]=an.x+0.5f*an.z; ay1[k]=an.y+0.5f*an.w;
        areaA[k]=(ax1[k]-ax0[k])*(ay1[k]-ay0[k]);
    }
    float best[4]={-1.f,-1.f,-1.f,-1.f}; int bg[4]={0,0,0,0};

    for (int g=0; g<NGG; ++g){
        float bi=-1.f; int bk=0;
        #pragma unroll
        for (int k=0;k<4;++k){
            float lx=fmaxf(ax0[k],gx0[g]), ly=fmaxf(ay0[k],gy0[g]);
            float rx=fminf(ax1[k],gx1[g]), ry=fminf(ay1[k],gy1[g]);
            float w=fmaxf(rx-lx,0.f), h=fmaxf(ry-ly,0.f);
            float inter=w*h;
            float uni=fmaxf(areaA[k]+garea[g]-inter, 1e-12f);
            float rcp; asm("rcp.approx.ftz.f32 %0, %1;" : "=f"(rcp) : "f"(uni));
            rcp = rcp * __fmaf_rn(-uni, rcp, 2.0f);     // Newton -> ~1ulp of div.rn
            float iou = inter * rcp;
            if (iou>best[k]){best[k]=iou; bg[k]=g;}
            if (iou>bi){bi=iou; bk=k;}
        }
        unsigned mb=__float_as_uint(bi);
        unsigned M=redux_max(mb);
        unsigned rk=(mb==M)? (unsigned)(((3-bk)<<5)|(31-(t&31)))+1u : 0u;
        unsigned R=redux_max(rk);
        if ((t&31)==0){
            int wl=31-(int)((R-1u)&31u), wk=3-(int)((R-1u)>>5);
            unsigned a=(unsigned)(blockIdx.x*1024 + (t&~31) + wl + wk*256);
            atomicMax(&skey[g], ((unsigned long long)M<<32) | (0xFFFFFFFFu - a));
        }
    }
    #pragma unroll
    for (int k=0;k<4;++k){
        bool pos = best[k] >= 0.5f;
        bool ign = (!pos) && (best[k] > 0.4f);
        unsigned char mB = (unsigned char)(bg[k] | (pos?0x80:(ign?0x40:0)));
        g_meta[b*NAA + abase + k*256] = mB;
    }
    __syncthreads();
    if (t<NGG) atomicMax(&g_bestkey[b*NGG+t], skey[t]);

    // ---- last block applies forced positives (replaces k_force launch) --------
    __threadfence();
    if (t==0) s_last = atomicAdd(&g_ctr1, 1);
    __syncthreads();
    if (s_last == 32*32 - 1){
        if (t==0) g_ctr1 = 0;                 // reset for next replay
        __threadfence();
        for (int i=t; i<BB*NGG; i+=256){
            unsigned long long k = g_bestkey[i];
            g_bestkey[i] = 0ull;              // reset for next replay
            unsigned a = 0xFFFFFFFFu - (unsigned)(k & 0xFFFFFFFFull);
            int bb = i / NGG;
            size_t idx = (size_t)bb*NAA + a;
            g_meta[idx] = (unsigned char)(g_meta[idx] | 0x80);  // benign dup race
        }
    }
}

// ---------------- K2: CE + classify + reg; 8 lanes/row, 4 rows per iter --------
__global__ void __launch_bounds__(256,5) k_main(const float* __restrict__ cls,
                                                const float* __restrict__ box,
                                                const float* __restrict__ anchors,
                                                const float* __restrict__ gtb,
                                                const int*   __restrict__ gtl){
    const int lane = threadIdx.x & 31;
    const int l8   = lane & 7;
    const int g    = lane >> 3;           // row within 4-row granule
    const int W = blockIdx.x*8 + (threadIdx.x>>5);
    const int b      = W / WPBATCH;
    const int within = W - b*WPBATCH;
    int lbeg = within*CHUNK;
    int lend = min(lbeg + CHUNK, PPB);
    if (lbeg >= lend) return;

    float l_np=0.f, l_ce=0.f, l_rg=0.f;
    const int pbeg = b*PPB + lbeg;        // global pair index (even)
    const int pend = b*PPB + lend;
    const float* rp = cls + (size_t)(2*pbeg + g)*81 + l8;
    const unsigned* meta32 = (const unsigned*)g_meta;

    for (int p = pbeg; p < pend; p += 2, rp += 324){
        unsigned mm = meta32[p>>1];       // 4 meta bytes = rows 2p..2p+3
        float v0=rp[0], v1=rp[8], v2=rp[16], v3=rp[24], v4=rp[32],
              v5=rp[40], v6=rp[48], v7=rp[56], v8=rp[64], v9=rp[72];
        float e0=__expf(v0), e1=__expf(v1), e2=__expf(v2), e3=__expf(v3), e4=__expf(v4);
        float e5=__expf(v5), e6=__expf(v6), e7=__expf(v7), e8=__expf(v8), e9=__expf(v9);
        float s = (((e0+e1)+(e2+e3)) + ((e4+e5)+(e6+e7))) + (e8+e9);
        if (l8==0) s += __expf(rp[80]);
        s += __shfl_xor_sync(0xFFFFFFFFu, s, 1);
        s += __shfl_xor_sync(0xFFFFFFFFu, s, 2);
        s += __shfl_xor_sync(0xFFFFFFFFu, s, 4);
        float lse = __logf(s);

        unsigned mb = (mm >> (g*8)) & 0xFFu;
        bool pos = (mb & 0x80u) != 0;
        bool ign = (mb & 0x40u) != 0;
        int row = 2*p + g;                // global row index

        if (l8==0){
            if (pos | ign) g_negbits[row] = SENT;
            else {
                float ce = fmaxf(lse - v0, 0.f);      // v0 = row[0] on leader
                unsigned bits = __float_as_uint(ce);
                g_negbits[row] = bits;
                atomicAdd(&g_hcnt[b*NBIN + (bits>>18)], 1u);
                atomicAdd(&g_hsum[b*NBIN + (bits>>18)], ce);
            }
        }
        if (__any_sync(0xFFFFFFFFu, pos)){            // rare branch
            if (l8==0 && pos){
                int gi = (int)(mb & 0x3Fu);
                int tgt = gtl[b*NGG + gi];
                float vt = cls[(size_t)row*81 + tgt]; // rare reload; off critical path
                int a = row & (NAA-1);
                l_np += 1.f;
                l_ce += fmaxf(lse - vt, 0.f);
                float4 an = ((const float4*)anchors)[a];
                float4 gt = ((const float4*)gtb)[b*NGG + gi];
                float tx = (gt.x - an.x) / an.z / 0.1f;
                float ty = (gt.y - an.y) / an.w / 0.1f;
                float tw = __logf(gt.z / an.z) / 0.2f;
                float th = __logf(gt.w / an.w) / 0.2f;
                float4 bp = ((const float4*)box)[row];
                float d0=bp.x-tx, d1=bp.y-ty, d2=bp.z-tw, d3=bp.w-th;
                float f0=fabsf(d0), f1=fabsf(d1), f2=fabsf(d2), f3=fabsf(d3);
                l_rg += ((f0<1.f)?0.5f*d0*d0:f0-0.5f) + ((f1<1.f)?0.5f*d1*d1:f1-0.5f)
                      + ((f2<1.f)?0.5f*d2*d2:f2-0.5f) + ((f3<1.f)?0.5f*d3*d3:f3-0.5f);
            }
        }
    }
    if (__any_sync(0xFFFFFFFFu, l_np != 0.f)){
        l_np += __shfl_xor_sync(0xFFFFFFFFu, l_np, 8);
        l_ce += __shfl_xor_sync(0xFFFFFFFFu, l_ce, 8);
        l_rg += __shfl_xor_sync(0xFFFFFFFFu, l_rg, 8);
        l_np += __shfl_xor_sync(0xFFFFFFFFu, l_np, 16);
        l_ce += __shfl_xor_sync(0xFFFFFFFFu, l_ce, 16);
        l_rg += __shfl_xor_sync(0xFFFFFFFFu, l_rg, 16);
        if (lane==0){
            atomicAdd(&g_numpos[b], l_np);
            atomicAdd(&g_posce[b],  l_ce);
            atomicAdd(&g_regsum[b], l_rg);
        }
    }
}

// ---------------- warp-scale select over 512 smem bins -------------------------
__device__ void warp_select(const unsigned* cnt, const float* fs, int K,
                            int* o_bin, int* o_k, float* o_S){
    int l = threadIdx.x;
    int base = l*16;
    unsigned c=0; float f=0.f;
    #pragma unroll
    for (int j=0;j<16;++j){ c+=cnt[base+j]; f+=fs[base+j]; }
    unsigned ci=c; float fi=f;
    #pragma unroll
    for (int off=1;off<32;off<<=1){
        unsigned uc=__shfl_up_sync(0xFFFFFFFFu,ci,off);
        float    uf=__shfl_up_sync(0xFFFFFFFFu,fi,off);
        if (l>=off){ ci+=uc; fi+=uf; }
    }
    unsigned total=__shfl_sync(0xFFFFFFFFu,ci,31);
    float    ftot =__shfl_sync(0xFFFFFFFFu,fi,31);
    unsigned SA=total-ci; float FA=ftot-fi;
    if (SA < (unsigned)K && (unsigned)K <= SA + c){
        unsigned run=SA; float fab=FA;
        for (int j=15;j>=0;--j){
            unsigned cb=cnt[base+j];
            if (run + cb >= (unsigned)K){ *o_bin=base+j; *o_k=(int)((unsigned)K-run); *o_S=fab; break; }
            run += cb; fab += fs[base+j];
        }
    }
}

// ---------------- K3: exact top-K + (last block) final reduce ------------------
__global__ void __launch_bounds__(1024) k_select(float* __restrict__ out){
    int b=blockIdx.x, t=threadIdx.x;
    int lane=t&31, warp=t>>5;
    unsigned* cnt = g_hcnt + b*NBIN;
    float*    fsm = g_hsum + b*NBIN;
    __shared__ unsigned swc[32]; __shared__ float swf[32];
    __shared__ int s_t1, s_k1;  __shared__ float s_S1;
    __shared__ int s_bin, s_k;  __shared__ float s_S;
    __shared__ int s_n, s_last;
    __shared__ unsigned cnt2[512]; __shared__ float fs2[512];
    __shared__ unsigned slist[CAP];

    // ---- level-1: this thread's 16 bins via 128-bit loads into registers ------
    int base = t*16;
    unsigned cb[16]; float fb[16];
    {
        const uint4*  c4 = (const uint4*) (cnt + base);
        const float4* f4 = (const float4*)(fsm + base);
        #pragma unroll
        for (int q=0;q<4;++q){
            uint4  u = c4[q];
            float4 gg = f4[q];
            cb[q*4+0]=u.x; cb[q*4+1]=u.y; cb[q*4+2]=u.z; cb[q*4+3]=u.w;
            fb[q*4+0]=gg.x; fb[q*4+1]=gg.y; fb[q*4+2]=gg.z; fb[q*4+3]=gg.w;
        }
    }
    unsigned c=0; float f=0.f;
    #pragma unroll
    for (int j=0;j<16;++j){ c+=cb[j]; f+=fb[j]; }
    unsigned ci=c; float fi=f;
    #pragma unroll
    for (int off=1;off<32;off<<=1){
        unsigned uc=__shfl_up_sync(0xFFFFFFFFu,ci,off);
        float    uf=__shfl_up_sync(0xFFFFFFFFu,fi,off);
        if (lane>=off){ ci+=uc; fi+=uf; }
    }
    if (lane==31){ swc[warp]=ci; swf[warp]=fi; }
    __syncthreads();
    if (t<32){
        unsigned u=swc[t]; float gg=swf[t];
        #pragma unroll
        for (int off=1;off<32;off<<=1){
            unsigned uu=__shfl_up_sync(0xFFFFFFFFu,u,off);
            float    g2=__shfl_up_sync(0xFFFFFFFFu,gg,off);
            if (t>=off){ u+=uu; gg+=g2; }
        }
        swc[t]=u; swf[t]=gg;
    }
    __syncthreads();
    unsigned P = ci + (warp ? swc[warp-1] : 0u);
    float    FP= fi + (warp ? swf[warp-1] : 0.f);
    unsigned total=swc[31]; float ftot=swf[31];

    float np = g_numpos[b];
    int negcnt = (int)total;
    int K = min(3*(int)np, negcnt);
    if (t==0) g_K[b] = K;

    if (K > 0){                              // block-uniform branch
        unsigned SA = total - P; float FA = ftot - FP;
        if (SA < (unsigned)K && (unsigned)K <= SA + c){
            unsigned run=SA; float fab=FA;
            #pragma unroll
            for (int j=15;j>=0;--j){
                unsigned cbj=cb[j];
                if (run + cbj >= (unsigned)K){ s_t1=base+j; s_k1=(int)((unsigned)K-run); s_S1=fab; break; }
                run += cbj; fab += fb[j];
            }
        }
        if (t==0) s_n=0;
        for (int i=t;i<512;i+=1024){ cnt2[i]=0u; fs2[i]=0.f; }
        __syncthreads();
        int t1=s_t1, k1=s_k1; float S1=s_S1;
        unsigned cT1 = cnt[t1];
        const unsigned* vals = g_negbits + b*NAA;
        bool collect = (cT1 <= CAP);
        if (collect){
            const uint4* v4 = (const uint4*)vals;
            for (int i=t;i<NAA/4;i+=1024){
                uint4 v = v4[i];
                if ((v.x>>18)==(unsigned)t1){ int p=atomicAdd(&s_n,1); slist[p]=v.x; }
                if ((v.y>>18)==(unsigned)t1){ int p=atomicAdd(&s_n,1); slist[p]=v.y; }
                if ((v.z>>18)==(unsigned)t1){ int p=atomicAdd(&s_n,1); slist[p]=v.z; }
                if ((v.w>>18)==(unsigned)t1){ int p=atomicAdd(&s_n,1); slist[p]=v.w; }
            }
        }
        __syncthreads();
        int n=s_n;
        if (collect){
            for (int i=t;i<n;i+=1024){
                unsigned v=slist[i];
                atomicAdd(&cnt2[(v>>9)&511u],1u); atomicAdd(&fs2[(v>>9)&511u],__uint_as_float(v));
            }
        } else {
            for (int i=t;i<NAA;i+=1024){
                unsigned v=vals[i];
                if ((v>>18)==(unsigned)t1){ atomicAdd(&cnt2[(v>>9)&511u],1u); atomicAdd(&fs2[(v>>9)&511u],__uint_as_float(v)); }
            }
        }
        __syncthreads();
        if (t<32) warp_select(cnt2, fs2, k1, &s_bin, &s_k, &s_S);
        __syncthreads();
        int t2=s_bin, k2=s_k; float S2=s_S;
        for (int i=t;i<512;i+=1024){ cnt2[i]=0u; fs2[i]=0.f; }
        __syncthreads();
        unsigned pfx = ((unsigned)t1<<9) | (unsigned)t2;
        if (collect){
            for (int i=t;i<n;i+=1024){
                unsigned v=slist[i];
                if ((v>>9)==pfx){ atomicAdd(&cnt2[v&511u],1u); atomicAdd(&fs2[v&511u],__uint_as_float(v)); }
            }
        } else {
            for (int i=t;i<NAA;i+=1024){
                unsigned v=vals[i];
                if ((v>>9)==pfx){ atomicAdd(&cnt2[v&511u],1u); atomicAdd(&fs2[v&511u],__uint_as_float(v)); }
            }
        }
        __syncthreads();
        if (t<32) warp_select(cnt2, fs2, k2, &s_bin, &s_k, &s_S);
        __syncthreads();
        if (t==0){
            unsigned tv = (pfx<<9) | (unsigned)s_bin;
            g_topk[b] = S1 + S2 + s_S + (float)s_k * __uint_as_float(tv);
        }
    } else {
        if (t==0) g_topk[b]=0.f;
    }

    // ---- reset this batch's hist (128-bit stores) -----------------------------
    {
        uint4*  c4 = (uint4*) (cnt + base);
        float4* f4 = (float4*)(fsm + base);
        uint4  uz = make_uint4(0u,0u,0u,0u);
        float4 fz = make_float4(0.f,0.f,0.f,0.f);
        #pragma unroll
        for (int q=0;q<4;++q){ c4[q]=uz; f4[q]=fz; }
    }

    // ---- last block performs the final reduce (replaces k_final launch) -------
    __threadfence();
    if (t==0) s_last = atomicAdd(&g_ctr2, 1);
    __syncthreads();
    if (s_last == BB-1){
        if (t==0) g_ctr2 = 0;                // reset for next replay
        __threadfence();
        if (t < 32){
            int bb = t;
            float npb = g_numpos[bb];
            float pcb = g_posce[bb];
            float rgb = g_regsum[bb];
            g_numpos[bb]=0.f; g_posce[bb]=0.f; g_regsum[bb]=0.f;
            int Kb = g_K[bb];
            float clsv = (Kb>0) ? (pcb + g_topk[bb]) / fmaxf(npb + (float)Kb, 1.f)
                                : pcb / fmaxf(npb, 1.f);
            float regv = rgb / fmaxf(npb*4.f, 1.f);   // num_pos >= 1 always
            #pragma unroll
            for (int off=16; off; off>>=1){
                clsv += __shfl_xor_sync(0xFFFFFFFFu, clsv, off);
                regv += __shfl_xor_sync(0xFFFFFFFFu, regv, off);
                npb  += __shfl_xor_sync(0xFFFFFFFFu, npb,  off);
            }
            if (t==0){
                out[0]=clsv/(float)BB; out[1]=regv/(float)BB; out[2]=npb/(float)BB;
            }
        }
    }
}

// ---------------- launch -------------------------------------------------------
extern "C" void kernel_launch(void* const* d_in, const int* in_sizes, int n_in,
                              void* d_out, int out_size) {
    const float* cls=nullptr; const float* box=nullptr; const float* anc=nullptr;
    const float* gtb=nullptr; const int* gtl=nullptr;
    for (int i=0;i<n_in;++i){
        long sz=in_sizes[i];
        if      (sz==(long)BB*NAA*CC) cls=(const float*)d_in[i];
        else if (sz==(long)BB*NAA*4)  box=(const float*)d_in[i];
        else if (sz==(long)NAA*4)     anc=(const float*)d_in[i];
        else if (sz==(long)BB*NGG*4)  gtb=(const float*)d_in[i];
        else if (sz==(long)BB*NGG)    gtl=(const int*)d_in[i];
    }
    k_iou<<<dim3(NAA/1024, BB), 256>>>(anc, gtb);
    k_main<<<MBLK, 256>>>(cls, box, anc, gtb, gtl);
    k_select<<<BB, 1024>>>((float*)d_out);
}